// round 2
// baseline (speedup 1.0000x reference)
#include <cuda_runtime.h>
#include <cstdint>
#include <math_constants.h>

namespace {

constexpr int B_  = 32768;
constexpr int A_  = 32;
constexpr int D_  = 64;
constexpr int H_  = 128;
constexpr int K_  = 128;   // 2*D context width
constexpr int TB  = 64;    // batch rows per block
constexpr int NT  = 256;   // threads per block
constexpr int WS  = 132;   // padded stride for transposed weight tiles

struct Smem {
  float ctx [TB][K_];   // [b][k] context
  float hctx[TB][H_];   // [b][h] ctx@Wc^T + br1
  float hid [TB][H_];   // [b][h] hidden for current action
  float wbuf[K_][WS];   // transposed weight: [k][m] (W1[a]^T / Wc^T / W2[a]^T)
  float wp  [D_][WS];   // [d][h] Wp^T
  float preds[TB][D_];  // [b][d] preds for current action
  float wr2 [H_];
  float bestr[TB];
  int   flags[TB];
};

// Transpose-load src[rows][cols] (row stride src_stride) into dst[c][r].
__device__ __forceinline__ void load_wT(float (*dst)[WS], const float* __restrict__ src,
                                        int rows, int cols, int src_stride, int tid) {
  int total4 = rows * cols / 4;
  for (int idx = tid; idx < total4; idx += NT) {
    int flat = idx * 4;
    int r = flat / cols;
    int c = flat - r * cols;
    float4 v = *reinterpret_cast<const float4*>(src + r * src_stride + c);
    dst[c + 0][r] = v.x;
    dst[c + 1][r] = v.y;
    dst[c + 2][r] = v.z;
    dst[c + 3][r] = v.w;
  }
}

// acc[4][8] += X[b0..b0+3][:] * W[:][m0..m0+7]   (X is [b][K] stride XS)
template <int K, int XS>
__device__ __forceinline__ void mm48(const float* __restrict__ X, const float (*W)[WS],
                                     int b0, int m0, float acc[4][8]) {
#pragma unroll
  for (int j = 0; j < 4; j++)
#pragma unroll
    for (int m = 0; m < 8; m++) acc[j][m] = 0.f;

#pragma unroll 4
  for (int k = 0; k < K; k++) {
    float x0 = X[(b0 + 0) * XS + k];
    float x1 = X[(b0 + 1) * XS + k];
    float x2 = X[(b0 + 2) * XS + k];
    float x3 = X[(b0 + 3) * XS + k];
    float4 wa = *reinterpret_cast<const float4*>(&W[k][m0]);
    float4 wb = *reinterpret_cast<const float4*>(&W[k][m0 + 4]);
    float w[8] = {wa.x, wa.y, wa.z, wa.w, wb.x, wb.y, wb.z, wb.w};
#pragma unroll
    for (int m = 0; m < 8; m++) {
      acc[0][m] = fmaf(x0, w[m], acc[0][m]);
      acc[1][m] = fmaf(x1, w[m], acc[1][m]);
      acc[2][m] = fmaf(x2, w[m], acc[2][m]);
      acc[3][m] = fmaf(x3, w[m], acc[3][m]);
    }
  }
}

// acc[4][4] += X[b0..b0+3][:] * W[:][m0..m0+3]
template <int K, int XS>
__device__ __forceinline__ void mm44(const float* __restrict__ X, const float (*W)[WS],
                                     int b0, int m0, float acc[4][4]) {
#pragma unroll
  for (int j = 0; j < 4; j++)
#pragma unroll
    for (int m = 0; m < 4; m++) acc[j][m] = 0.f;

#pragma unroll 4
  for (int k = 0; k < K; k++) {
    float x0 = X[(b0 + 0) * XS + k];
    float x1 = X[(b0 + 1) * XS + k];
    float x2 = X[(b0 + 2) * XS + k];
    float x3 = X[(b0 + 3) * XS + k];
    float4 wa = *reinterpret_cast<const float4*>(&W[k][m0]);
    float w[4] = {wa.x, wa.y, wa.z, wa.w};
#pragma unroll
    for (int m = 0; m < 4; m++) {
      acc[0][m] = fmaf(x0, w[m], acc[0][m]);
      acc[1][m] = fmaf(x1, w[m], acc[1][m]);
      acc[2][m] = fmaf(x2, w[m], acc[2][m]);
      acc[3][m] = fmaf(x3, w[m], acc[3][m]);
    }
  }
}

}  // namespace

extern "C" __global__ void __launch_bounds__(NT, 1)
cmb_fused_kernel(const int* __restrict__ x, const int* __restrict__ y,
                 const float* __restrict__ cemb, const float* __restrict__ wemb,
                 const float* __restrict__ W1, const float* __restrict__ b1,
                 const float* __restrict__ W2, const float* __restrict__ b2,
                 const float* __restrict__ Wr1, const float* __restrict__ br1,
                 const float* __restrict__ Wr2, const float* __restrict__ br2,
                 float* __restrict__ out) {
  extern __shared__ char smraw[];
  Smem& sm = *reinterpret_cast<Smem*>(smraw);
  const int tid = threadIdx.x;
  const int b0g = blockIdx.x * TB;
  (void)br2;  // constant offset — irrelevant for argmin

  // ---- Phase 0: gather ctx rows, copy wemb rows, init small arrays ----
  {
    int b = tid >> 2;          // 0..63
    int part = tid & 3;        // 4 threads per batch row
    int gb = b0g + b;
    int x0 = x[gb * 2 + 0];
    int x1 = x[gb * 2 + 1];
#pragma unroll
    for (int q = 0; q < 8; q++) {
      int k = part * 32 + q * 4;
      const float* src = (k < 64) ? (cemb + (size_t)x0 * 64 + k)
                                  : (cemb + (size_t)x1 * 64 + (k - 64));
      *reinterpret_cast<float4*>(&sm.ctx[b][k]) =
          *reinterpret_cast<const float4*>(src);
    }
    int yy = y[gb];
#pragma unroll
    for (int q = 0; q < 4; q++) {
      int d = part * 16 + q * 4;
      *reinterpret_cast<float4*>(&out[(size_t)B_ * 64 + (size_t)gb * 64 + d]) =
          *reinterpret_cast<const float4*>(wemb + (size_t)yy * 64 + d);
    }
  }
  if (tid < TB) sm.bestr[tid] = CUDART_INF_F;
  if (tid < H_) sm.wr2[tid] = Wr2[tid];

  // Wc^T into wbuf (Wr1[:, :128], row stride 192), Wp^T into wp
  load_wT(sm.wbuf, Wr1, H_, K_, 192, tid);
  load_wT(sm.wp, Wr1 + 128, H_, D_, 192, tid);
  __syncthreads();

  const int btile = tid >> 4;        // 0..15, 4 batch rows each
  const int mtile = tid & 15;        // 0..15
  const int bb = btile * 4;

  // ---- Phase 1: hctx = ctx @ Wc^T + br1 ----
  {
    int m0 = mtile * 8;
    float acc[4][8];
    mm48<K_, K_>(&sm.ctx[0][0], sm.wbuf, bb, m0, acc);
#pragma unroll
    for (int j = 0; j < 4; j++)
#pragma unroll
      for (int m = 0; m < 8; m++)
        sm.hctx[bb + j][m0 + m] = acc[j][m] + br1[m0 + m];
  }
  __syncthreads();

  // ---- Action loop ----
  for (int a = 0; a < A_; a++) {
    // W1[a]^T into wbuf
    load_wT(sm.wbuf, W1 + (size_t)a * H_ * K_, H_, K_, K_, tid);
    __syncthreads();

    // hidden = ctx @ W1[a]^T + b1[a]
    {
      int m0 = mtile * 8;
      float acc[4][8];
      mm48<K_, K_>(&sm.ctx[0][0], sm.wbuf, bb, m0, acc);
#pragma unroll
      for (int j = 0; j < 4; j++)
#pragma unroll
        for (int m = 0; m < 8; m++)
          sm.hid[bb + j][m0 + m] = acc[j][m] + b1[a * H_ + m0 + m];
    }
    __syncthreads();

    // W2[a]^T into wbuf (W2[a] is [d][h])
    load_wT(sm.wbuf, W2 + (size_t)a * D_ * H_, D_, H_, H_, tid);
    __syncthreads();

    // preds = hidden @ W2[a]^T + b2[a]
    {
      int d0 = mtile * 4;
      float acc[4][4];
      mm44<H_, H_>(&sm.hid[0][0], sm.wbuf, bb, d0, acc);
#pragma unroll
      for (int j = 0; j < 4; j++)
#pragma unroll
        for (int m = 0; m < 4; m++)
          sm.preds[bb + j][d0 + m] = acc[j][m] + b2[a * D_ + d0 + m];
    }
    __syncthreads();

    // reward = sum_h relu(hctx + preds @ Wp^T) * Wr2
    {
      int m0 = mtile * 8;
      float acc[4][8];
      mm48<D_, D_>(&sm.preds[0][0], sm.wp, bb, m0, acc);
      float part[4];
#pragma unroll
      for (int j = 0; j < 4; j++) {
        float s = 0.f;
#pragma unroll
        for (int m = 0; m < 8; m++) {
          float h2 = acc[j][m] + sm.hctx[bb + j][m0 + m];
          h2 = fmaxf(h2, 0.f);
          s = fmaf(h2, sm.wr2[m0 + m], s);
        }
        part[j] = s;
      }
      // reduce over the 16 threads sharing this btile (lane groups of 16)
#pragma unroll
      for (int off = 8; off >= 1; off >>= 1)
#pragma unroll
        for (int j = 0; j < 4; j++)
          part[j] += __shfl_xor_sync(0xffffffffu, part[j], off);
      if (mtile == 0) {
#pragma unroll
        for (int j = 0; j < 4; j++) {
          int b = bb + j;
          if (part[j] < sm.bestr[b]) {  // strict < => first-min wins (matches argmin)
            sm.bestr[b] = part[j];
            sm.flags[b] = 1;
          } else {
            sm.flags[b] = 0;
          }
        }
      }
    }
    __syncthreads();

    // copy-on-improve: winning preds row -> out
    {
      int b = tid >> 2;
      int part_ = tid & 3;
      if (sm.flags[b]) {
        int gb = b0g + b;
#pragma unroll
        for (int q = 0; q < 4; q++) {
          int d = part_ * 16 + q * 4;
          *reinterpret_cast<float4*>(&out[(size_t)gb * 64 + d]) =
              *reinterpret_cast<const float4*>(&sm.preds[b][d]);
        }
      }
    }
    __syncthreads();
  }
}

extern "C" void kernel_launch(void* const* d_in, const int* in_sizes, int n_in,
                              void* d_out, int out_size) {
  (void)in_sizes; (void)n_in; (void)out_size;
  const int*   x    = (const int*)d_in[0];
  const int*   y    = (const int*)d_in[1];
  const float* cemb = (const float*)d_in[2];
  const float* wemb = (const float*)d_in[3];
  const float* W1   = (const float*)d_in[4];
  const float* b1   = (const float*)d_in[5];
  const float* W2   = (const float*)d_in[6];
  const float* b2   = (const float*)d_in[7];
  const float* Wr1  = (const float*)d_in[8];
  const float* br1  = (const float*)d_in[9];
  const float* Wr2  = (const float*)d_in[10];
  const float* br2  = (const float*)d_in[11];
  float* out = (float*)d_out;

  static_assert(sizeof(Smem) <= 227 * 1024, "smem budget");
  cudaFuncSetAttribute(cmb_fused_kernel,
                       cudaFuncAttributeMaxDynamicSharedMemorySize,
                       (int)sizeof(Smem));
  cmb_fused_kernel<<<B_ / TB, NT, sizeof(Smem)>>>(
      x, y, cemb, wemb, W1, b1, W2, b2, Wr1, br1, Wr2, br2, out);
}

// round 3
// speedup vs baseline: 3.0577x; 3.0577x over previous
#include <cuda_runtime.h>
#include <cstdint>

namespace {

constexpr int B_  = 32768;
constexpr int A_  = 32;
constexpr int D_  = 64;    // pred dim
constexpr int H_  = 128;   // hidden dim
constexpr int K_  = 128;   // 2*D context width
constexpr int TB  = 64;    // batch rows per block
constexpr int NT  = 256;   // threads per block

struct Smem {
  float ctx  [TB][K_];   // 32 KB  [b][k]
  float wbuf [K_][D_];   // 32 KB  WeffT[a]: [k][d]   (also WcT halves: [k][h'])
  float wpT  [D_][H_];   // 32 KB  [d][h]
  float preds[TB][D_];   // 16 KB  [b][d]
  float bestr[TB];
  int   flags[TB];
};

}  // namespace

// Scratch for fused weights (allowed: __device__ globals, no runtime alloc)
__device__ float g_weffT[A_ * K_ * D_];   // [a][k][d]  1 MB
__device__ float g_beff [A_ * D_];        // [a][d]

// ---------------------------------------------------------------------------
// Precompute: WeffT[a][k][d] = sum_h W2[a][d][h] * W1[a][h][k]
//             beff[a][d]     = sum_h W2[a][d][h] * b1[a][h] + b2[a][d]
// ---------------------------------------------------------------------------
__global__ void __launch_bounds__(NT)
cmb_precompute_kernel(const float* __restrict__ W1, const float* __restrict__ b1,
                      const float* __restrict__ W2, const float* __restrict__ b2) {
  __shared__ float w1s[H_][K_];  // [h][k] 64 KB
  __shared__ float w2s[D_][H_];  // [d][h] 32 KB
  const int a   = blockIdx.x;
  const int tid = threadIdx.x;
  const float* W1a = W1 + (size_t)a * H_ * K_;
  const float* W2a = W2 + (size_t)a * D_ * H_;

  for (int i = tid; i < H_ * K_ / 4; i += NT)
    reinterpret_cast<float4*>(&w1s[0][0])[i] =
        reinterpret_cast<const float4*>(W1a)[i];
  for (int i = tid; i < D_ * H_ / 4; i += NT)
    reinterpret_cast<float4*>(&w2s[0][0])[i] =
        reinterpret_cast<const float4*>(W2a)[i];
  __syncthreads();

  // thread -> (k-quad, 8 d's)
  const int kq = tid & 31;   // k0 = 4*kq
  const int dt = tid >> 5;   // d0 = 8*dt
  const int k0 = kq * 4, d0 = dt * 8;

  float acc[4][8];
#pragma unroll
  for (int i = 0; i < 4; i++)
#pragma unroll
    for (int j = 0; j < 8; j++) acc[i][j] = 0.f;

  for (int h = 0; h < H_; h++) {
    float4 w1v = *reinterpret_cast<const float4*>(&w1s[h][k0]);
    float w1x[4] = {w1v.x, w1v.y, w1v.z, w1v.w};
#pragma unroll
    for (int j = 0; j < 8; j++) {
      float w2v = w2s[d0 + j][h];   // broadcast within warp
#pragma unroll
      for (int i = 0; i < 4; i++) acc[i][j] = fmaf(w2v, w1x[i], acc[i][j]);
    }
  }

  float* dst = g_weffT + (size_t)a * K_ * D_;
#pragma unroll
  for (int i = 0; i < 4; i++) {
#pragma unroll
    for (int j = 0; j < 8; j += 4) {
      float4 v = make_float4(acc[i][j], acc[i][j + 1], acc[i][j + 2], acc[i][j + 3]);
      *reinterpret_cast<float4*>(&dst[(k0 + i) * D_ + d0 + j]) = v;
    }
  }

  if (tid < D_) {
    float s = b2[a * D_ + tid];
    for (int h = 0; h < H_; h++) s = fmaf(w2s[tid][h], b1[a * H_ + h], s);
    g_beff[a * D_ + tid] = s;
  }
}

// ---------------------------------------------------------------------------
// Main fused kernel
// ---------------------------------------------------------------------------
__global__ void __launch_bounds__(NT, 2)
cmb_fused_kernel(const int* __restrict__ x, const int* __restrict__ y,
                 const float* __restrict__ cemb, const float* __restrict__ wemb,
                 const float* __restrict__ Wr1, const float* __restrict__ br1,
                 const float* __restrict__ Wr2,
                 float* __restrict__ out) {
  extern __shared__ char smraw[];
  Smem& sm = *reinterpret_cast<Smem*>(smraw);
  const int tid = threadIdx.x;
  const int b0g = blockIdx.x * TB;

  // ---- Prologue: gather ctx rows, write wemb output, init ----
  {
    int b = tid >> 2, part = tid & 3;
    int gb = b0g + b;
    int x0 = x[gb * 2 + 0];
    int x1 = x[gb * 2 + 1];
#pragma unroll
    for (int q = 0; q < 8; q++) {
      int k = part * 32 + q * 4;
      const float* src = (k < 64) ? (cemb + (size_t)x0 * 64 + k)
                                  : (cemb + (size_t)x1 * 64 + (k - 64));
      *reinterpret_cast<float4*>(&sm.ctx[b][k]) =
          *reinterpret_cast<const float4*>(src);
    }
    int yy = y[gb];
#pragma unroll
    for (int q = 0; q < 4; q++) {
      int d = part * 16 + q * 4;
      *reinterpret_cast<float4*>(&out[(size_t)B_ * 64 + (size_t)gb * 64 + d]) =
          *reinterpret_cast<const float4*>(wemb + (size_t)yy * 64 + d);
    }
  }
  if (tid < TB) sm.bestr[tid] = 3.0e38f;

  // WpT[d][h] = Wr1[h][128 + d]
  for (int i = tid; i < H_ * (D_ / 4); i += NT) {
    int h = i >> 4, q = i & 15;
    float4 v = *reinterpret_cast<const float4*>(&Wr1[h * 192 + 128 + q * 4]);
    sm.wpT[q * 4 + 0][h] = v.x;
    sm.wpT[q * 4 + 1][h] = v.y;
    sm.wpT[q * 4 + 2][h] = v.z;
    sm.wpT[q * 4 + 3][h] = v.w;
  }

  const int btile = tid >> 4;       // 0..15
  const int mtile = tid & 15;       // 0..15
  const int bb = btile * 4;
  const int d0 = mtile * 4;         // GEMM1 d-tile
  const int h0 = mtile * 4;         // GEMM2 h-tile (+64 for second half)

  // Wr2 into registers (order matches acc2 slot order)
  float wr2r[8];
#pragma unroll
  for (int m = 0; m < 4; m++) {
    wr2r[m]     = Wr2[h0 + m];
    wr2r[4 + m] = Wr2[h0 + 64 + m];
  }

  // ---- hctx (+br1) in registers, via two WcT half-passes through wbuf ----
  float hctxr[4][8];
#pragma unroll
  for (int pass = 0; pass < 2; pass++) {
    __syncthreads();
    // wbuf[k][h'] = Wr1[pass*64 + h'][k],  h' in [0,64)
    for (int i = tid; i < 64 * (K_ / 4); i += NT) {
      int hp = i >> 5, q = i & 31;
      float4 v = *reinterpret_cast<const float4*>(&Wr1[(pass * 64 + hp) * 192 + q * 4]);
      sm.wbuf[q * 4 + 0][hp] = v.x;
      sm.wbuf[q * 4 + 1][hp] = v.y;
      sm.wbuf[q * 4 + 2][hp] = v.z;
      sm.wbuf[q * 4 + 3][hp] = v.w;
    }
    __syncthreads();

    float acc[4][4];
#pragma unroll
    for (int j = 0; j < 4; j++)
#pragma unroll
      for (int m = 0; m < 4; m++) acc[j][m] = 0.f;

    for (int k = 0; k < K_; k += 4) {
      float xv[4][4];
#pragma unroll
      for (int j = 0; j < 4; j++) {
        float4 v = *reinterpret_cast<const float4*>(&sm.ctx[bb + j][k]);
        xv[j][0] = v.x; xv[j][1] = v.y; xv[j][2] = v.z; xv[j][3] = v.w;
      }
#pragma unroll
      for (int kk = 0; kk < 4; kk++) {
        float4 w = *reinterpret_cast<const float4*>(&sm.wbuf[k + kk][h0]);
        float wm[4] = {w.x, w.y, w.z, w.w};
#pragma unroll
        for (int j = 0; j < 4; j++)
#pragma unroll
          for (int m = 0; m < 4; m++)
            acc[j][m] = fmaf(xv[j][kk], wm[m], acc[j][m]);
      }
    }
#pragma unroll
    for (int j = 0; j < 4; j++)
#pragma unroll
      for (int m = 0; m < 4; m++)
        hctxr[j][pass * 4 + m] = acc[j][m] + br1[pass * 64 + h0 + m];
  }

  // ---- Action loop ----
  for (int a = 0; a < A_; a++) {
    __syncthreads();   // flags/preds of a-1 ready; wbuf free

    // copy-on-improve for action a-1
    if (a > 0) {
      int b = tid >> 2, part = tid & 3;
      if (sm.flags[b]) {
        int gb = b0g + b;
#pragma unroll
        for (int q = 0; q < 4; q++) {
          int d = part * 16 + q * 4;
          *reinterpret_cast<float4*>(&out[(size_t)gb * 64 + d]) =
              *reinterpret_cast<const float4*>(&sm.preds[b][d]);
        }
      }
    }

    // load WeffT[a] into wbuf (identical [k][d] layout, straight copy)
    {
      const float4* src = reinterpret_cast<const float4*>(g_weffT + (size_t)a * K_ * D_);
      float4* dst = reinterpret_cast<float4*>(&sm.wbuf[0][0]);
      for (int i = tid; i < K_ * D_ / 4; i += NT) dst[i] = src[i];
    }
    float4 beffv = *reinterpret_cast<const float4*>(&g_beff[a * D_ + d0]);
    float beffr[4] = {beffv.x, beffv.y, beffv.z, beffv.w};

    __syncthreads();

    // GEMM1: preds[b][d] = ctx[b][:] @ WeffT[:, d] + beff
    {
      float acc[4][4];
#pragma unroll
      for (int j = 0; j < 4; j++)
#pragma unroll
        for (int m = 0; m < 4; m++) acc[j][m] = 0.f;

      for (int k = 0; k < K_; k += 4) {
        float xv[4][4];
#pragma unroll
        for (int j = 0; j < 4; j++) {
          float4 v = *reinterpret_cast<const float4*>(&sm.ctx[bb + j][k]);
          xv[j][0] = v.x; xv[j][1] = v.y; xv[j][2] = v.z; xv[j][3] = v.w;
        }
#pragma unroll
        for (int kk = 0; kk < 4; kk++) {
          float4 w = *reinterpret_cast<const float4*>(&sm.wbuf[k + kk][d0]);
          float wm[4] = {w.x, w.y, w.z, w.w};
#pragma unroll
          for (int j = 0; j < 4; j++)
#pragma unroll
            for (int m = 0; m < 4; m++)
              acc[j][m] = fmaf(xv[j][kk], wm[m], acc[j][m]);
        }
      }
#pragma unroll
      for (int j = 0; j < 4; j++) {
        float4 o = make_float4(acc[j][0] + beffr[0], acc[j][1] + beffr[1],
                               acc[j][2] + beffr[2], acc[j][3] + beffr[3]);
        *reinterpret_cast<float4*>(&sm.preds[bb + j][d0]) = o;
      }
    }
    __syncthreads();

    // GEMM2 + reward: h2 = relu(hctx + preds @ WpT); r = h2 . wr2
    {
      float acc[4][8];
#pragma unroll
      for (int j = 0; j < 4; j++)
#pragma unroll
        for (int m = 0; m < 8; m++) acc[j][m] = 0.f;

      for (int k = 0; k < D_; k += 4) {
        float xv[4][4];
#pragma unroll
        for (int j = 0; j < 4; j++) {
          float4 v = *reinterpret_cast<const float4*>(&sm.preds[bb + j][k]);
          xv[j][0] = v.x; xv[j][1] = v.y; xv[j][2] = v.z; xv[j][3] = v.w;
        }
#pragma unroll
        for (int kk = 0; kk < 4; kk++) {
          float4 wa = *reinterpret_cast<const float4*>(&sm.wpT[k + kk][h0]);
          float4 wb = *reinterpret_cast<const float4*>(&sm.wpT[k + kk][h0 + 64]);
          float wm[8] = {wa.x, wa.y, wa.z, wa.w, wb.x, wb.y, wb.z, wb.w};
#pragma unroll
          for (int j = 0; j < 4; j++)
#pragma unroll
            for (int m = 0; m < 8; m++)
              acc[j][m] = fmaf(xv[j][kk], wm[m], acc[j][m]);
        }
      }

      float part[4];
#pragma unroll
      for (int j = 0; j < 4; j++) {
        float s = 0.f;
#pragma unroll
        for (int m = 0; m < 8; m++) {
          float h2 = acc[j][m] + hctxr[j][m];
          h2 = fmaxf(h2, 0.f);
          s = fmaf(h2, wr2r[m], s);
        }
        part[j] = s;
      }
#pragma unroll
      for (int off = 8; off >= 1; off >>= 1)
#pragma unroll
        for (int j = 0; j < 4; j++)
          part[j] += __shfl_xor_sync(0xffffffffu, part[j], off);

      if (mtile == 0) {
#pragma unroll
        for (int j = 0; j < 4; j++) {
          int b = bb + j;
          if (part[j] < sm.bestr[b]) {   // strict <  => first-min wins
            sm.bestr[b] = part[j];
            sm.flags[b] = 1;
          } else {
            sm.flags[b] = 0;
          }
        }
      }
    }
  }

  __syncthreads();
  // final copy-on-improve (action 31)
  {
    int b = tid >> 2, part = tid & 3;
    if (sm.flags[b]) {
      int gb = b0g + b;
#pragma unroll
      for (int q = 0; q < 4; q++) {
        int d = part * 16 + q * 4;
        *reinterpret_cast<float4*>(&out[(size_t)gb * 64 + d]) =
            *reinterpret_cast<const float4*>(&sm.preds[b][d]);
      }
    }
  }
}

extern "C" void kernel_launch(void* const* d_in, const int* in_sizes, int n_in,
                              void* d_out, int out_size) {
  (void)in_sizes; (void)n_in; (void)out_size;
  const int*   x    = (const int*)d_in[0];
  const int*   y    = (const int*)d_in[1];
  const float* cemb = (const float*)d_in[2];
  const float* wemb = (const float*)d_in[3];
  const float* W1   = (const float*)d_in[4];
  const float* b1   = (const float*)d_in[5];
  const float* W2   = (const float*)d_in[6];
  const float* b2   = (const float*)d_in[7];
  const float* Wr1  = (const float*)d_in[8];
  const float* br1  = (const float*)d_in[9];
  const float* Wr2  = (const float*)d_in[10];
  float* out = (float*)d_out;

  static_assert(sizeof(Smem) <= 116 * 1024, "smem budget for 2 blocks/SM");
  cudaFuncSetAttribute(cmb_fused_kernel,
                       cudaFuncAttributeMaxDynamicSharedMemorySize,
                       (int)sizeof(Smem));

  cmb_precompute_kernel<<<A_, NT>>>(W1, b1, W2, b2);
  cmb_fused_kernel<<<B_ / TB, NT, sizeof(Smem)>>>(
      x, y, cemb, wemb, Wr1, br1, Wr2, out);
}

// round 4
// speedup vs baseline: 3.5515x; 1.1615x over previous
#include <cuda_runtime.h>
#include <cstdint>

namespace {

constexpr int B_  = 32768;
constexpr int A_  = 32;
constexpr int D_  = 64;    // pred dim
constexpr int H_  = 128;   // hidden dim
constexpr int K_  = 128;   // 2*D context width
constexpr int TB  = 64;    // batch rows per block
constexpr int NT  = 256;   // threads per block

struct Smem {
  float ctx  [TB][K_];   // 32 KB  [b][k]
  float wbuf [K_][D_];   // 32 KB  WeffT[a]: [k][d]   (also WcT halves)
  float wpT  [D_][H_];   // 32 KB  [d][h]
  float preds[TB][D_];   // 16 KB  [b][d]
  float bestr[TB];
  int   flags[TB];
};

using u64 = unsigned long long;

// packed helpers ------------------------------------------------------------
__device__ __forceinline__ u64 pack_dup(float x) {
  u64 r;
  asm("mov.b64 %0, {%1, %1};" : "=l"(r) : "f"(x));
  return r;
}
__device__ __forceinline__ u64 pack2(float a, float b) {
  u64 r;
  asm("mov.b64 %0, {%1, %2};" : "=l"(r) : "f"(a), "f"(b));
  return r;
}
__device__ __forceinline__ void ffma2(u64& d, u64 a, u64 b) {
  asm("fma.rn.f32x2 %0, %1, %2, %0;" : "+l"(d) : "l"(a), "l"(b));
}
__device__ __forceinline__ u64 fadd2(u64 a, u64 b) {
  u64 r;
  asm("add.rn.f32x2 %0, %1, %2;" : "=l"(r) : "l"(a), "l"(b));
  return r;
}
__device__ __forceinline__ void unpack2(u64 v, float& lo, float& hi) {
  asm("mov.b64 {%0, %1}, %2;" : "=f"(lo), "=f"(hi) : "l"(v));
}

}  // namespace

// Scratch for fused weights (allowed: __device__ globals)
__device__ float g_weffT[A_ * K_ * D_];   // [a][k][d]
__device__ float g_beff [A_ * D_];        // [a][d]

// ---------------------------------------------------------------------------
// Precompute: WeffT[a][k][d] = sum_h W2[a][d][h] * W1[a][h][k]
//             beff[a][d]     = sum_h W2[a][d][h] * b1[a][h] + b2[a][d]
// ---------------------------------------------------------------------------
__global__ void __launch_bounds__(NT)
cmb_precompute_kernel(const float* __restrict__ W1, const float* __restrict__ b1,
                      const float* __restrict__ W2, const float* __restrict__ b2) {
  __shared__ float w1s[H_][K_];
  __shared__ float w2s[D_][H_];
  const int a   = blockIdx.x;
  const int tid = threadIdx.x;
  const float* W1a = W1 + (size_t)a * H_ * K_;
  const float* W2a = W2 + (size_t)a * D_ * H_;

  for (int i = tid; i < H_ * K_ / 4; i += NT)
    reinterpret_cast<float4*>(&w1s[0][0])[i] =
        reinterpret_cast<const float4*>(W1a)[i];
  for (int i = tid; i < D_ * H_ / 4; i += NT)
    reinterpret_cast<float4*>(&w2s[0][0])[i] =
        reinterpret_cast<const float4*>(W2a)[i];
  __syncthreads();

  const int kq = tid & 31;
  const int dt = tid >> 5;
  const int k0 = kq * 4, d0 = dt * 8;

  float acc[4][8];
#pragma unroll
  for (int i = 0; i < 4; i++)
#pragma unroll
    for (int j = 0; j < 8; j++) acc[i][j] = 0.f;

  for (int h = 0; h < H_; h++) {
    float4 w1v = *reinterpret_cast<const float4*>(&w1s[h][k0]);
    float w1x[4] = {w1v.x, w1v.y, w1v.z, w1v.w};
#pragma unroll
    for (int j = 0; j < 8; j++) {
      float w2v = w2s[d0 + j][h];
#pragma unroll
      for (int i = 0; i < 4; i++) acc[i][j] = fmaf(w2v, w1x[i], acc[i][j]);
    }
  }

  float* dst = g_weffT + (size_t)a * K_ * D_;
#pragma unroll
  for (int i = 0; i < 4; i++) {
#pragma unroll
    for (int j = 0; j < 8; j += 4) {
      float4 v = make_float4(acc[i][j], acc[i][j + 1], acc[i][j + 2], acc[i][j + 3]);
      *reinterpret_cast<float4*>(&dst[(k0 + i) * D_ + d0 + j]) = v;
    }
  }

  if (tid < D_) {
    float s = b2[a * D_ + tid];
    for (int h = 0; h < H_; h++) s = fmaf(w2s[tid][h], b1[a * H_ + h], s);
    g_beff[a * D_ + tid] = s;
  }
}

// ---------------------------------------------------------------------------
// Main fused kernel (FFMA2 / f32x2 packed math)
// ---------------------------------------------------------------------------
__global__ void __launch_bounds__(NT, 2)
cmb_fused_kernel(const int* __restrict__ x, const int* __restrict__ y,
                 const float* __restrict__ cemb, const float* __restrict__ wemb,
                 const float* __restrict__ Wr1, const float* __restrict__ br1,
                 const float* __restrict__ Wr2,
                 float* __restrict__ out) {
  extern __shared__ char smraw[];
  Smem& sm = *reinterpret_cast<Smem*>(smraw);
  const int tid = threadIdx.x;
  const int b0g = blockIdx.x * TB;

  // ---- Prologue: gather ctx rows, write wemb output, init ----
  {
    int b = tid >> 2, part = tid & 3;
    int gb = b0g + b;
    int x0 = x[gb * 2 + 0];
    int x1 = x[gb * 2 + 1];
#pragma unroll
    for (int q = 0; q < 8; q++) {
      int k = part * 32 + q * 4;
      const float* src = (k < 64) ? (cemb + (size_t)x0 * 64 + k)
                                  : (cemb + (size_t)x1 * 64 + (k - 64));
      *reinterpret_cast<float4*>(&sm.ctx[b][k]) =
          *reinterpret_cast<const float4*>(src);
    }
    int yy = y[gb];
#pragma unroll
    for (int q = 0; q < 4; q++) {
      int d = part * 16 + q * 4;
      *reinterpret_cast<float4*>(&out[(size_t)B_ * 64 + (size_t)gb * 64 + d]) =
          *reinterpret_cast<const float4*>(wemb + (size_t)yy * 64 + d);
    }
  }
  if (tid < TB) sm.bestr[tid] = 3.0e38f;

  // WpT[d][h] = Wr1[h][128 + d]
  for (int i = tid; i < H_ * (D_ / 4); i += NT) {
    int h = i >> 4, q = i & 15;
    float4 v = *reinterpret_cast<const float4*>(&Wr1[h * 192 + 128 + q * 4]);
    sm.wpT[q * 4 + 0][h] = v.x;
    sm.wpT[q * 4 + 1][h] = v.y;
    sm.wpT[q * 4 + 2][h] = v.z;
    sm.wpT[q * 4 + 3][h] = v.w;
  }

  const int btile = tid >> 4;       // 0..15
  const int mtile = tid & 15;       // 0..15
  const int bb = btile * 4;
  const int d0 = mtile * 4;         // GEMM1 d-tile
  const int h0 = mtile * 4;         // GEMM2 h-tile (+64 second half)

  // Wr2 into registers (slot order: h0..h0+3, h0+64..h0+67)
  float wr2r[8];
#pragma unroll
  for (int m = 0; m < 4; m++) {
    wr2r[m]     = Wr2[h0 + m];
    wr2r[4 + m] = Wr2[h0 + 64 + m];
  }

  // ---- hctx (+br1): two WcT half-passes (scalar; one-time cost) ----
  float hctxr[4][8];
#pragma unroll
  for (int pass = 0; pass < 2; pass++) {
    __syncthreads();
    for (int i = tid; i < 64 * (K_ / 4); i += NT) {
      int hp = i >> 5, q = i & 31;
      float4 v = *reinterpret_cast<const float4*>(&Wr1[(pass * 64 + hp) * 192 + q * 4]);
      sm.wbuf[q * 4 + 0][hp] = v.x;
      sm.wbuf[q * 4 + 1][hp] = v.y;
      sm.wbuf[q * 4 + 2][hp] = v.z;
      sm.wbuf[q * 4 + 3][hp] = v.w;
    }
    __syncthreads();

    float acc[4][4];
#pragma unroll
    for (int j = 0; j < 4; j++)
#pragma unroll
      for (int m = 0; m < 4; m++) acc[j][m] = 0.f;

    for (int k = 0; k < K_; k += 4) {
      float xv[4][4];
#pragma unroll
      for (int j = 0; j < 4; j++) {
        float4 v = *reinterpret_cast<const float4*>(&sm.ctx[bb + j][k]);
        xv[j][0] = v.x; xv[j][1] = v.y; xv[j][2] = v.z; xv[j][3] = v.w;
      }
#pragma unroll
      for (int kk = 0; kk < 4; kk++) {
        float4 w = *reinterpret_cast<const float4*>(&sm.wbuf[k + kk][h0]);
        float wm[4] = {w.x, w.y, w.z, w.w};
#pragma unroll
        for (int j = 0; j < 4; j++)
#pragma unroll
          for (int m = 0; m < 4; m++)
            acc[j][m] = fmaf(xv[j][kk], wm[m], acc[j][m]);
      }
    }
#pragma unroll
    for (int j = 0; j < 4; j++)
#pragma unroll
      for (int m = 0; m < 4; m++)
        hctxr[j][pass * 4 + m] = acc[j][m] + br1[pass * 64 + h0 + m];
  }

  // pack hctx into f32x2 pairs: [j][p] = (hctxr[j][2p], hctxr[j][2p+1])
  u64 hctx2[4][4];
#pragma unroll
  for (int j = 0; j < 4; j++)
#pragma unroll
    for (int p = 0; p < 4; p++)
      hctx2[j][p] = pack2(hctxr[j][2 * p], hctxr[j][2 * p + 1]);

  // ---- Action loop ----
  for (int a = 0; a < A_; a++) {
    __syncthreads();   // flags/preds of a-1 consumed; wbuf free

    // copy-on-improve for action a-1
    if (a > 0) {
      int b = tid >> 2, part = tid & 3;
      if (sm.flags[b]) {
        int gb = b0g + b;
#pragma unroll
        for (int q = 0; q < 4; q++) {
          int d = part * 16 + q * 4;
          *reinterpret_cast<float4*>(&out[(size_t)gb * 64 + d]) =
              *reinterpret_cast<const float4*>(&sm.preds[b][d]);
        }
      }
    }

    // load WeffT[a] into wbuf
    {
      const float4* src = reinterpret_cast<const float4*>(g_weffT + (size_t)a * K_ * D_);
      float4* dst = reinterpret_cast<float4*>(&sm.wbuf[0][0]);
      for (int i = tid; i < K_ * D_ / 4; i += NT) dst[i] = src[i];
    }
    u64 beff2[2];
    {
      const u64* bp = reinterpret_cast<const u64*>(&g_beff[a * D_ + d0]);
      beff2[0] = bp[0];
      beff2[1] = bp[1];
    }
    __syncthreads();

    // GEMM1: preds[b][d] = ctx[b][:] @ WeffT[:, d] + beff   (f32x2)
    {
      u64 acc2[4][2];
#pragma unroll
      for (int j = 0; j < 4; j++) { acc2[j][0] = 0ull; acc2[j][1] = 0ull; }

      for (int k = 0; k < K_; k += 4) {
        float xv[4][4];
#pragma unroll
        for (int j = 0; j < 4; j++) {
          float4 v = *reinterpret_cast<const float4*>(&sm.ctx[bb + j][k]);
          xv[j][0] = v.x; xv[j][1] = v.y; xv[j][2] = v.z; xv[j][3] = v.w;
        }
#pragma unroll
        for (int kk = 0; kk < 4; kk++) {
          ulonglong2 w = *reinterpret_cast<const ulonglong2*>(&sm.wbuf[k + kk][d0]);
#pragma unroll
          for (int j = 0; j < 4; j++) {
            u64 xd = pack_dup(xv[j][kk]);
            ffma2(acc2[j][0], xd, w.x);
            ffma2(acc2[j][1], xd, w.y);
          }
        }
      }
#pragma unroll
      for (int j = 0; j < 4; j++) {
        ulonglong2 o;
        o.x = fadd2(acc2[j][0], beff2[0]);
        o.y = fadd2(acc2[j][1], beff2[1]);
        *reinterpret_cast<ulonglong2*>(&sm.preds[bb + j][d0]) = o;
      }
    }
    __syncthreads();

    // GEMM2 + reward: h2 = relu(hctx + preds @ WpT); r = h2 . wr2   (f32x2)
    {
      u64 acc2[4][4];
#pragma unroll
      for (int j = 0; j < 4; j++)
#pragma unroll
        for (int p = 0; p < 4; p++) acc2[j][p] = 0ull;

      for (int k = 0; k < D_; k += 4) {
        float xv[4][4];
#pragma unroll
        for (int j = 0; j < 4; j++) {
          float4 v = *reinterpret_cast<const float4*>(&sm.preds[bb + j][k]);
          xv[j][0] = v.x; xv[j][1] = v.y; xv[j][2] = v.z; xv[j][3] = v.w;
        }
#pragma unroll
        for (int kk = 0; kk < 4; kk++) {
          ulonglong2 wa = *reinterpret_cast<const ulonglong2*>(&sm.wpT[k + kk][h0]);
          ulonglong2 wb = *reinterpret_cast<const ulonglong2*>(&sm.wpT[k + kk][h0 + 64]);
#pragma unroll
          for (int j = 0; j < 4; j++) {
            u64 xd = pack_dup(xv[j][kk]);
            ffma2(acc2[j][0], xd, wa.x);
            ffma2(acc2[j][1], xd, wa.y);
            ffma2(acc2[j][2], xd, wb.x);
            ffma2(acc2[j][3], xd, wb.y);
          }
        }
      }

      float part[4];
#pragma unroll
      for (int j = 0; j < 4; j++) {
        float s = 0.f;
#pragma unroll
        for (int p = 0; p < 4; p++) {
          u64 v = fadd2(acc2[j][p], hctx2[j][p]);
          float lo, hi;
          unpack2(v, lo, hi);
          lo = fmaxf(lo, 0.f);
          hi = fmaxf(hi, 0.f);
          s = fmaf(lo, wr2r[2 * p], s);
          s = fmaf(hi, wr2r[2 * p + 1], s);
        }
        part[j] = s;
      }
#pragma unroll
      for (int off = 8; off >= 1; off >>= 1)
#pragma unroll
        for (int j = 0; j < 4; j++)
          part[j] += __shfl_xor_sync(0xffffffffu, part[j], off);

      if (mtile == 0) {
#pragma unroll
        for (int j = 0; j < 4; j++) {
          int b = bb + j;
          if (part[j] < sm.bestr[b]) {   // strict <  => first-min wins
            sm.bestr[b] = part[j];
            sm.flags[b] = 1;
          } else {
            sm.flags[b] = 0;
          }
        }
      }
    }
  }

  __syncthreads();
  // final copy-on-improve (action 31)
  {
    int b = tid >> 2, part = tid & 3;
    if (sm.flags[b]) {
      int gb = b0g + b;
#pragma unroll
      for (int q = 0; q < 4; q++) {
        int d = part * 16 + q * 4;
        *reinterpret_cast<float4*>(&out[(size_t)gb * 64 + d]) =
            *reinterpret_cast<const float4*>(&sm.preds[b][d]);
      }
    }
  }
}

extern "C" void kernel_launch(void* const* d_in, const int* in_sizes, int n_in,
                              void* d_out, int out_size) {
  (void)in_sizes; (void)n_in; (void)out_size;
  const int*   x    = (const int*)d_in[0];
  const int*   y    = (const int*)d_in[1];
  const float* cemb = (const float*)d_in[2];
  const float* wemb = (const float*)d_in[3];
  const float* W1   = (const float*)d_in[4];
  const float* b1   = (const float*)d_in[5];
  const float* W2   = (const float*)d_in[6];
  const float* b2   = (const float*)d_in[7];
  const float* Wr1  = (const float*)d_in[8];
  const float* br1  = (const float*)d_in[9];
  const float* Wr2  = (const float*)d_in[10];
  float* out = (float*)d_out;

  static_assert(sizeof(Smem) <= 116 * 1024, "smem budget for 2 blocks/SM");
  cudaFuncSetAttribute(cmb_fused_kernel,
                       cudaFuncAttributeMaxDynamicSharedMemorySize,
                       (int)sizeof(Smem));

  cmb_precompute_kernel<<<A_, NT>>>(W1, b1, W2, b2);
  cmb_fused_kernel<<<B_ / TB, NT, sizeof(Smem)>>>(
      x, y, cemb, wemb, Wr1, br1, Wr2, out);
}